// round 2
// baseline (speedup 1.0000x reference)
#include <cuda_runtime.h>

// Kalman predict: x_hat = Ap x ; P_hat = Ap P Ap^T + Q,  Ap = triu(relu(A))
// One thread per batch element. Ap strict-lower entries are compile-time 0
// after full unroll, so dead FMAs are eliminated.

__global__ void __launch_bounds__(256)
kf_predict_kernel(const float* __restrict__ x,
                  const float* __restrict__ P,
                  const float* __restrict__ A,
                  const float* __restrict__ sigma_p,
                  const float* __restrict__ sigma_v,
                  float* __restrict__ x_hat,
                  float* __restrict__ P_hat,
                  int B)
{
    int b = blockIdx.x * blockDim.x + threadIdx.x;
    if (b >= B) return;

    // ---- Ap = triu(relu(A)) : broadcast loads, L1/L2 resident ----
    float ap[8][8];
#pragma unroll
    for (int i = 0; i < 8; i++) {
#pragma unroll
        for (int j = 0; j < 8; j++) {
            ap[i][j] = (j >= i) ? fmaxf(__ldg(&A[i * 8 + j]), 0.0f) : 0.0f;
        }
    }
    const float sp = __ldg(sigma_p);
    const float sv = __ldg(sigma_v);

    // ---- load x (8 floats, 2x float4) ----
    float xv[8];
    {
        const float4* x4 = reinterpret_cast<const float4*>(x + (size_t)b * 8);
        float4 a0 = __ldg(x4 + 0);
        float4 a1 = __ldg(x4 + 1);
        xv[0] = a0.x; xv[1] = a0.y; xv[2] = a0.z; xv[3] = a0.w;
        xv[4] = a1.x; xv[5] = a1.y; xv[6] = a1.z; xv[7] = a1.w;
    }

    // ---- x_hat = Ap x ----
    float xh[8];
#pragma unroll
    for (int i = 0; i < 8; i++) {
        float s = 0.0f;
#pragma unroll
        for (int j = 0; j < 8; j++) {
            if (j >= i) s = fmaf(ap[i][j], xv[j], s);
        }
        xh[i] = s;
    }
    {
        float4* o4 = reinterpret_cast<float4*>(x_hat + (size_t)b * 8);
        o4[0] = make_float4(xh[0], xh[1], xh[2], xh[3]);
        o4[1] = make_float4(xh[4], xh[5], xh[6], xh[7]);
    }

    // ---- load P (64 floats, 16x float4) ----
    float p[8][8];
    {
        const float4* p4 = reinterpret_cast<const float4*>(P + (size_t)b * 64);
#pragma unroll
        for (int r = 0; r < 8; r++) {
            float4 lo = __ldg(p4 + r * 2 + 0);
            float4 hi = __ldg(p4 + r * 2 + 1);
            p[r][0] = lo.x; p[r][1] = lo.y; p[r][2] = lo.z; p[r][3] = lo.w;
            p[r][4] = hi.x; p[r][5] = hi.y; p[r][6] = hi.z; p[r][7] = hi.w;
        }
    }

    // ---- stage 1: P <- Ap * P  (in place: row i reads rows j >= i) ----
#pragma unroll
    for (int i = 0; i < 8; i++) {
        float t[8];
#pragma unroll
        for (int k = 0; k < 8; k++) {
            float s = 0.0f;
#pragma unroll
            for (int j = 0; j < 8; j++) {
                if (j >= i) s = fmaf(ap[i][j], p[j][k], s);
            }
            t[k] = s;
        }
#pragma unroll
        for (int k = 0; k < 8; k++) p[i][k] = t[k];
    }

    // ---- stage 2: P <- P * Ap^T (in place: out col l reads cols k >= l) ----
#pragma unroll
    for (int i = 0; i < 8; i++) {
        float t[8];
#pragma unroll
        for (int l = 0; l < 8; l++) {
            float s = 0.0f;
#pragma unroll
            for (int k = 0; k < 8; k++) {
                if (k >= l) s = fmaf(p[i][k], ap[l][k], s);
            }
            t[l] = s;
        }
#pragma unroll
        for (int l = 0; l < 8; l++) p[i][l] = t[l];
    }

    // ---- Q: diag = [h*sp, w*sp, h*sp, w*sp, h*sv, w*sv, h*sv, w*sv]^2 ----
    {
        const float h = xv[2];
        const float w = xv[3];
        float d[8];
        d[0] = h * sp; d[1] = w * sp; d[2] = h * sp; d[3] = w * sp;
        d[4] = h * sv; d[5] = w * sv; d[6] = h * sv; d[7] = w * sv;
#pragma unroll
        for (int i = 0; i < 8; i++) p[i][i] = fmaf(d[i], d[i], p[i][i]);
    }

    // ---- store P_hat (16x float4) ----
    {
        float4* o4 = reinterpret_cast<float4*>(P_hat + (size_t)b * 64);
#pragma unroll
        for (int r = 0; r < 8; r++) {
            o4[r * 2 + 0] = make_float4(p[r][0], p[r][1], p[r][2], p[r][3]);
            o4[r * 2 + 1] = make_float4(p[r][4], p[r][5], p[r][6], p[r][7]);
        }
    }
}

extern "C" void kernel_launch(void* const* d_in, const int* in_sizes, int n_in,
                              void* d_out, int out_size)
{
    const float* x  = (const float*)d_in[0];   // (B, 8, 1)
    const float* P  = (const float*)d_in[1];   // (B, 8, 8)
    const float* A  = (const float*)d_in[2];   // (8, 8)
    const float* sp = (const float*)d_in[3];   // scalar
    const float* sv = (const float*)d_in[4];   // scalar

    const int B = in_sizes[0] / 8;

    float* out   = (float*)d_out;
    float* x_hat = out;                        // B*8 floats
    float* P_hat = out + (size_t)B * 8;        // B*64 floats

    const int threads = 256;
    const int blocks = (B + threads - 1) / threads;
    kf_predict_kernel<<<blocks, threads>>>(x, P, A, sp, sv, x_hat, P_hat, B);
}